// round 1
// baseline (speedup 1.0000x reference)
#include <cuda_runtime.h>

#define N_NODES 8192
#define FIN 256
#define FOUT 64
#define GAT_ALPHA 0.2f

// Scratch (allocation-free rule: __device__ globals)
__device__ float g_h[(size_t)N_NODES * FOUT];   // 2 MB
__device__ float g_s1[N_NODES];
__device__ float g_s2[N_NODES];

// ---------------------------------------------------------------------------
// Kernel 1: h = input @ W ; s1 = h @ a1 ; s2 = h @ a2
// One block per node row, 64 threads (one per output feature).
// ---------------------------------------------------------------------------
__global__ __launch_bounds__(FOUT) void k_compute_h(
    const float* __restrict__ input,   // [N, FIN]
    const float* __restrict__ W,       // [FIN, FOUT]
    const float* __restrict__ a)       // [2*FOUT]
{
    const int i = blockIdx.x;
    const int f = threadIdx.x;  // 0..63

    __shared__ float srow[FIN];
    #pragma unroll
    for (int k = f; k < FIN; k += FOUT)
        srow[k] = input[(size_t)i * FIN + k];
    __syncthreads();

    float acc = 0.0f;
    #pragma unroll 8
    for (int k = 0; k < FIN; ++k)
        acc = fmaf(srow[k], __ldg(&W[k * FOUT + f]), acc);

    g_h[(size_t)i * FOUT + f] = acc;

    __shared__ float r1[FOUT];
    __shared__ float r2[FOUT];
    r1[f] = acc * __ldg(&a[f]);
    r2[f] = acc * __ldg(&a[FOUT + f]);
    __syncthreads();
    #pragma unroll
    for (int s = 32; s > 0; s >>= 1) {
        if (f < s) { r1[f] += r1[f + s]; r2[f] += r2[f + s]; }
        __syncthreads();
    }
    if (f == 0) { g_s1[i] = r1[0]; g_s2[i] = r2[0]; }
}

// ---------------------------------------------------------------------------
// Kernel 2: per-row masked softmax + attention @ h + elu, fused.
// One block (256 threads) per row i. e_row kept in smem (32 KB).
// ---------------------------------------------------------------------------
__global__ __launch_bounds__(256) void k_attn(
    const int* __restrict__ adj,       // [N, N]
    float* __restrict__ out)           // [N, FOUT]
{
    const int i = blockIdx.x;
    const int tid = threadIdx.x;

    __shared__ float e_row[N_NODES];   // 32 KB
    __shared__ float red[256];
    __shared__ float s_m, s_l;

    const float s1 = g_s1[i];
    const int* __restrict__ arow = adj + (size_t)i * N_NODES;

    // --- Phase A1: build e_row, per-thread max ---
    float m = -1e30f;
    #pragma unroll 4
    for (int j = tid; j < N_NODES; j += 256) {
        float x = s1 + g_s2[j];
        float e = x > 0.0f ? x : GAT_ALPHA * x;
        e = (arow[j] > 0) ? e : -10.0f;
        e_row[j] = e;
        m = fmaxf(m, e);
    }
    red[tid] = m;
    __syncthreads();
    #pragma unroll
    for (int s = 128; s > 0; s >>= 1) {
        if (tid < s) red[tid] = fmaxf(red[tid], red[tid + s]);
        __syncthreads();
    }
    if (tid == 0) s_m = red[0];
    __syncthreads();
    m = s_m;

    // --- Phase A2: denominator l = sum exp(e - m) over ALL j (masked ones
    //     contribute exp(-10 - m), matching the reference exactly) ---
    float l = 0.0f;
    #pragma unroll 4
    for (int j = tid; j < N_NODES; j += 256)
        l += __expf(e_row[j] - m);
    __syncthreads();   // red reuse
    red[tid] = l;
    __syncthreads();
    #pragma unroll
    for (int s = 128; s > 0; s >>= 1) {
        if (tid < s) red[tid] += red[tid + s];
        __syncthreads();
    }
    if (tid == 0) s_l = red[0];
    __syncthreads();
    l = s_l;
    const float inv_l = 1.0f / l;

    // --- Phase B: acc[f] = sum_j exp(e_j - m) * h[j][f] ---
    // Thread layout: f4 = tid&15 (4 features via float4), jg = tid>>4 (16 j-groups)
    const int f4 = tid & 15;
    const int jg = tid >> 4;
    const float4* __restrict__ h4 = reinterpret_cast<const float4*>(g_h);

    float4 acc = make_float4(0.f, 0.f, 0.f, 0.f);
    const int jbeg = jg * (N_NODES / 16);
    const int jend = jbeg + (N_NODES / 16);
    for (int j = jbeg; j < jend; j += 4) {
        float4 ev = *reinterpret_cast<const float4*>(&e_row[j]);
        float w0 = __expf(ev.x - m);
        float w1 = __expf(ev.y - m);
        float w2 = __expf(ev.z - m);
        float w3 = __expf(ev.w - m);
        float4 h0 = h4[(size_t)(j + 0) * 16 + f4];
        float4 h1 = h4[(size_t)(j + 1) * 16 + f4];
        float4 h2 = h4[(size_t)(j + 2) * 16 + f4];
        float4 h3 = h4[(size_t)(j + 3) * 16 + f4];
        acc.x = fmaf(w0, h0.x, acc.x);
        acc.y = fmaf(w0, h0.y, acc.y);
        acc.z = fmaf(w0, h0.z, acc.z);
        acc.w = fmaf(w0, h0.w, acc.w);
        acc.x = fmaf(w1, h1.x, acc.x);
        acc.y = fmaf(w1, h1.y, acc.y);
        acc.z = fmaf(w1, h1.z, acc.z);
        acc.w = fmaf(w1, h1.w, acc.w);
        acc.x = fmaf(w2, h2.x, acc.x);
        acc.y = fmaf(w2, h2.y, acc.y);
        acc.z = fmaf(w2, h2.z, acc.z);
        acc.w = fmaf(w2, h2.w, acc.w);
        acc.x = fmaf(w3, h3.x, acc.x);
        acc.y = fmaf(w3, h3.y, acc.y);
        acc.z = fmaf(w3, h3.z, acc.z);
        acc.w = fmaf(w3, h3.w, acc.w);
    }

    // --- Combine the 16 j-groups and apply softmax normalization + elu ---
    __syncthreads();                     // done reading e_row; reuse as scratch
    float* sc = e_row;
    sc[jg * FOUT + f4 * 4 + 0] = acc.x;
    sc[jg * FOUT + f4 * 4 + 1] = acc.y;
    sc[jg * FOUT + f4 * 4 + 2] = acc.z;
    sc[jg * FOUT + f4 * 4 + 3] = acc.w;
    __syncthreads();

    if (tid < FOUT) {
        float s = 0.0f;
        #pragma unroll
        for (int g = 0; g < 16; ++g)
            s += sc[g * FOUT + tid];
        float v = s * inv_l;
        out[(size_t)i * FOUT + tid] = (v > 0.0f) ? v : (__expf(v) - 1.0f);
    }
}

// ---------------------------------------------------------------------------
extern "C" void kernel_launch(void* const* d_in, const int* in_sizes, int n_in,
                              void* d_out, int out_size)
{
    const float* input = (const float*)d_in[0];  // [8192, 256]
    const int*   adj   = (const int*)  d_in[1];  // [8192, 8192]
    const float* W     = (const float*)d_in[2];  // [256, 64]
    const float* a     = (const float*)d_in[3];  // [128, 1]
    float* out = (float*)d_out;                  // [8192, 64]

    k_compute_h<<<N_NODES, FOUT>>>(input, W, a);
    k_attn<<<N_NODES, 256>>>(adj, out);
}

// round 2
// speedup vs baseline: 2.0994x; 2.0994x over previous
#include <cuda_runtime.h>

#define N_NODES 8192
#define FIN 256
#define FOUT 64
#define GAT_ALPHA 0.2f
#define EXP_M10 4.539992976e-5f   // expf(-10)

#define TI 64
#define TJ 64
#define JSPLIT 8
#define JCHUNK (N_NODES / JSPLIT)   // 1024
#define NTILES (JCHUNK / TJ)        // 16

// Scratch (allocation-free rule: __device__ globals)
__device__ float g_h[(size_t)N_NODES * FOUT];            // 2 MB
__device__ float g_s1[N_NODES];
__device__ float g_s2[N_NODES];
__device__ float g_part[JSPLIT][N_NODES][FOUT];          // 16 MB
__device__ float g_lpart[JSPLIT][N_NODES];               // 256 KB

// ---------------------------------------------------------------------------
// Kernel 1: h = input @ W ; s1 = h @ a1 ; s2 = h @ a2
// ---------------------------------------------------------------------------
__global__ __launch_bounds__(FOUT) void k_compute_h(
    const float* __restrict__ input,   // [N, FIN]
    const float* __restrict__ W,       // [FIN, FOUT]
    const float* __restrict__ a)       // [2*FOUT]
{
    const int i = blockIdx.x;
    const int f = threadIdx.x;  // 0..63

    __shared__ float srow[FIN];
    #pragma unroll
    for (int k = f; k < FIN; k += FOUT)
        srow[k] = input[(size_t)i * FIN + k];
    __syncthreads();

    float acc = 0.0f;
    #pragma unroll 8
    for (int k = 0; k < FIN; ++k)
        acc = fmaf(srow[k], __ldg(&W[k * FOUT + f]), acc);

    g_h[(size_t)i * FOUT + f] = acc;

    __shared__ float r1[FOUT];
    __shared__ float r2[FOUT];
    r1[f] = acc * __ldg(&a[f]);
    r2[f] = acc * __ldg(&a[FOUT + f]);
    __syncthreads();
    #pragma unroll
    for (int s = 32; s > 0; s >>= 1) {
        if (f < s) { r1[f] += r1[f + s]; r2[f] += r2[f + s]; }
        __syncthreads();
    }
    if (f == 0) { g_s1[i] = r1[0]; g_s2[i] = r2[0]; }
}

// ---------------------------------------------------------------------------
// Kernel 2: register-tiled partial GEMM  part = exp(e) @ h  (+ partial l)
// Grid: (128 i-tiles, 8 j-splits), 128 threads.
// No max subtraction: e <= ~15 so exp(e) is fp32-safe; identical softmax result.
// ---------------------------------------------------------------------------
__global__ __launch_bounds__(128) void k_gemm(const int* __restrict__ adj)
{
    const int it = blockIdx.x;          // 0..127
    const int js = blockIdx.y;          // 0..7
    const int i0 = it * TI;
    const int j0 = js * JCHUNK;
    const int t  = threadIdx.x;

    __shared__ float h_s[TJ][FOUT];     // 16 KB
    __shared__ float w_s[TJ][TI];       // 16 KB
    __shared__ float s1_s[TI];
    __shared__ float s2_s[JCHUNK];      // 4 KB: all s2 for this j-chunk
    __shared__ float l_s[TI];

    // --- CTA-wide staging of s1 tile and s2 chunk ---
    if (t < TI) s1_s[t] = g_s1[i0 + t];
    #pragma unroll
    for (int r = t; r < JCHUNK; r += 128)
        s2_s[r] = g_s2[j0 + r];

    // build-phase mapping: 2 threads per i-row, each covers 32 j's (8 int4)
    const int i_loc = t >> 1;           // 0..63
    const int jh    = (t & 1) * 32;     // 0 or 32

    // FMA-phase mapping: 4i x 8f register tile
    const int ig4 = (t >> 3) * 4;       // i offset: 0,4,...,60
    const int fg8 = (t & 7) * 8;        // f offset: 0,8,...,56

    float4 a0a = {0,0,0,0}, a0b = {0,0,0,0};
    float4 a1a = {0,0,0,0}, a1b = {0,0,0,0};
    float4 a2a = {0,0,0,0}, a2b = {0,0,0,0};
    float4 a3a = {0,0,0,0}, a3b = {0,0,0,0};
    float l_loc = 0.0f;

    __syncthreads();
    const float s1v = s1_s[i_loc];

    for (int tile = 0; tile < NTILES; ++tile) {
        const int jt = tile * TJ;       // local offset within chunk

        __syncthreads();   // previous FMA phase done reading smem

        // --- stage h tile [TJ][FOUT] (contiguous 16 KB) ---
        {
            const float4* hsrc = reinterpret_cast<const float4*>(
                g_h + (size_t)(j0 + jt) * FOUT);
            float4* hdst = reinterpret_cast<float4*>(&h_s[0][0]);
            #pragma unroll
            for (int r = 0; r < 8; ++r)
                hdst[t + r * 128] = hsrc[t + r * 128];
        }

        // --- build w tile: w[j][i] = adj ? exp(lrelu(s1+s2)) : exp(-10) ---
        {
            const int4* arow = reinterpret_cast<const int4*>(
                adj + (size_t)(i0 + i_loc) * N_NODES + (j0 + jt + jh));
            #pragma unroll
            for (int q = 0; q < 8; ++q) {
                const int4 av = arow[q];
                const int jj = jh + q * 4;
                float x, e, w;

                x = s1v + s2_s[jt + jj + 0];
                e = x > 0.0f ? x : GAT_ALPHA * x;
                w = (av.x > 0) ? __expf(e) : EXP_M10;
                w_s[jj + 0][i_loc] = w; l_loc += w;

                x = s1v + s2_s[jt + jj + 1];
                e = x > 0.0f ? x : GAT_ALPHA * x;
                w = (av.y > 0) ? __expf(e) : EXP_M10;
                w_s[jj + 1][i_loc] = w; l_loc += w;

                x = s1v + s2_s[jt + jj + 2];
                e = x > 0.0f ? x : GAT_ALPHA * x;
                w = (av.z > 0) ? __expf(e) : EXP_M10;
                w_s[jj + 2][i_loc] = w; l_loc += w;

                x = s1v + s2_s[jt + jj + 3];
                e = x > 0.0f ? x : GAT_ALPHA * x;
                w = (av.w > 0) ? __expf(e) : EXP_M10;
                w_s[jj + 3][i_loc] = w; l_loc += w;
            }
        }

        __syncthreads();   // w_s, h_s ready

        // --- FMA phase: 4i x 8f per thread over TJ j's ---
        #pragma unroll 8
        for (int j = 0; j < TJ; ++j) {
            const float4 w4 = *reinterpret_cast<const float4*>(&w_s[j][ig4]);
            const float4 ha = *reinterpret_cast<const float4*>(&h_s[j][fg8]);
            const float4 hb = *reinterpret_cast<const float4*>(&h_s[j][fg8 + 4]);

            a0a.x = fmaf(w4.x, ha.x, a0a.x); a0a.y = fmaf(w4.x, ha.y, a0a.y);
            a0a.z = fmaf(w4.x, ha.z, a0a.z); a0a.w = fmaf(w4.x, ha.w, a0a.w);
            a0b.x = fmaf(w4.x, hb.x, a0b.x); a0b.y = fmaf(w4.x, hb.y, a0b.y);
            a0b.z = fmaf(w4.x, hb.z, a0b.z); a0b.w = fmaf(w4.x, hb.w, a0b.w);

            a1a.x = fmaf(w4.y, ha.x, a1a.x); a1a.y = fmaf(w4.y, ha.y, a1a.y);
            a1a.z = fmaf(w4.y, ha.z, a1a.z); a1a.w = fmaf(w4.y, ha.w, a1a.w);
            a1b.x = fmaf(w4.y, hb.x, a1b.x); a1b.y = fmaf(w4.y, hb.y, a1b.y);
            a1b.z = fmaf(w4.y, hb.z, a1b.z); a1b.w = fmaf(w4.y, hb.w, a1b.w);

            a2a.x = fmaf(w4.z, ha.x, a2a.x); a2a.y = fmaf(w4.z, ha.y, a2a.y);
            a2a.z = fmaf(w4.z, ha.z, a2a.z); a2a.w = fmaf(w4.z, ha.w, a2a.w);
            a2b.x = fmaf(w4.z, hb.x, a2b.x); a2b.y = fmaf(w4.z, hb.y, a2b.y);
            a2b.z = fmaf(w4.z, hb.z, a2b.z); a2b.w = fmaf(w4.z, hb.w, a2b.w);

            a3a.x = fmaf(w4.w, ha.x, a3a.x); a3a.y = fmaf(w4.w, ha.y, a3a.y);
            a3a.z = fmaf(w4.w, ha.z, a3a.z); a3a.w = fmaf(w4.w, ha.w, a3a.w);
            a3b.x = fmaf(w4.w, hb.x, a3b.x); a3b.y = fmaf(w4.w, hb.y, a3b.y);
            a3b.z = fmaf(w4.w, hb.z, a3b.z); a3b.w = fmaf(w4.w, hb.w, a3b.w);
        }
    }

    // --- write output partials ---
    {
        float* base = &g_part[js][i0 + ig4][0] + fg8;
        *reinterpret_cast<float4*>(base + 0 * FOUT)     = a0a;
        *reinterpret_cast<float4*>(base + 0 * FOUT + 4) = a0b;
        *reinterpret_cast<float4*>(base + 1 * FOUT)     = a1a;
        *reinterpret_cast<float4*>(base + 1 * FOUT + 4) = a1b;
        *reinterpret_cast<float4*>(base + 2 * FOUT)     = a2a;
        *reinterpret_cast<float4*>(base + 2 * FOUT + 4) = a2b;
        *reinterpret_cast<float4*>(base + 3 * FOUT)     = a3a;
        *reinterpret_cast<float4*>(base + 3 * FOUT + 4) = a3b;
    }

    // --- combine the 2 per-i l contributions and write l partial ---
    __syncthreads();
    if ((t & 1) == 0) l_s[i_loc] = l_loc;
    __syncthreads();
    if ((t & 1) == 1) l_s[i_loc] += l_loc;
    __syncthreads();
    if (t < TI) g_lpart[js][i0 + t] = l_s[t];
}

// ---------------------------------------------------------------------------
// Kernel 3: reduce partials, normalize, ELU
// ---------------------------------------------------------------------------
__global__ __launch_bounds__(256) void k_reduce(float* __restrict__ out)
{
    const int idx = blockIdx.x * 256 + threadIdx.x;   // over N*FOUT
    const int i = idx >> 6;
    const int f = idx & 63;

    float s = 0.0f, l = 0.0f;
    #pragma unroll
    for (int p = 0; p < JSPLIT; ++p) {
        s += g_part[p][i][f];
        l += g_lpart[p][i];
    }
    const float v = s / l;
    out[idx] = (v > 0.0f) ? v : (__expf(v) - 1.0f);
}

// ---------------------------------------------------------------------------
extern "C" void kernel_launch(void* const* d_in, const int* in_sizes, int n_in,
                              void* d_out, int out_size)
{
    const float* input = (const float*)d_in[0];  // [8192, 256]
    const int*   adj   = (const int*)  d_in[1];  // [8192, 8192]
    const float* W     = (const float*)d_in[2];  // [256, 64]
    const float* a     = (const float*)d_in[3];  // [128, 1]
    float* out = (float*)d_out;                  // [8192, 64]

    k_compute_h<<<N_NODES, FOUT>>>(input, W, a);
    k_gemm<<<dim3(N_NODES / TI, JSPLIT), 128>>>(adj);
    k_reduce<<<(N_NODES * FOUT) / 256, 256>>>(out);
}

// round 4
// speedup vs baseline: 5.1417x; 2.4491x over previous
#include <cuda_runtime.h>
#include <cstdint>

#define N_NODES 8192
#define FIN 256
#define FOUT 64
#define GAT_ALPHA 0.2f
#define EXP_M10 4.539992976e-5f   // expf(-10)

// ---- k_mma geometry ----
#define TM 128                       // i rows per CTA
#define TKJ 64                       // j per tile
#define JSPLIT 4
#define KCHUNK (N_NODES / JSPLIT)    // 2048
#define NT (KCHUNK / TKJ)            // 32 tiles

// padded smem rows: 68 floats -> bank-conflict-free frag loads
#define A_STRIDE 68
#define B_STRIDE 68
#define SM_B_OFF (TM * A_STRIDE)                  // 8704 floats
#define SMEM_FLOATS (SM_B_OFF + TKJ * B_STRIDE)   // 13056 floats
#define SMEM_BYTES (SMEM_FLOATS * 4)              // 52224 B

// ---- scratch (allocation-free rule) ----
__device__ float g_s1[N_NODES];
__device__ float g_s2[N_NODES];
__device__ float g_hf32[(size_t)N_NODES * FOUT];   // tf32-rounded h, 2 MB
__device__ float g_part[JSPLIT][N_NODES][FOUT];    // 8 MB
__device__ float g_lpart[JSPLIT][N_NODES];         // 128 KB

__device__ __forceinline__ float tf32r(float x) {
    uint32_t r;
    asm("cvt.rna.tf32.f32 %0, %1;" : "=r"(r) : "f"(x));
    return __uint_as_float(r);
}

__device__ __forceinline__ void mma_tf32(float c[4],
    uint32_t a0, uint32_t a1, uint32_t a2, uint32_t a3,
    uint32_t b0, uint32_t b1)
{
    asm volatile(
        "mma.sync.aligned.m16n8k8.row.col.f32.tf32.tf32.f32 "
        "{%0,%1,%2,%3}, {%4,%5,%6,%7}, {%8,%9}, {%0,%1,%2,%3};"
        : "+f"(c[0]), "+f"(c[1]), "+f"(c[2]), "+f"(c[3])
        : "r"(a0), "r"(a1), "r"(a2), "r"(a3), "r"(b0), "r"(b1));
}

// ============================================================================
// Kernel 1: h = input @ W (smem-tiled, fp32); emit s1, s2 (fp32 exact)
// and g_hf32 = tf32-rounded h. Grid: 128 blocks x 64 rows, 256 threads.
// ============================================================================
__global__ __launch_bounds__(256) void k_h(
    const float* __restrict__ input,   // [N, FIN]
    const float* __restrict__ W,       // [FIN, FOUT]
    const float* __restrict__ a)       // [2*FOUT]
{
    __shared__ float pool[8192];       // in_s[64][64] | w_s[64][64]; reused h_s[64][65]
    const int t = threadIdx.x;
    const int i0 = blockIdx.x * 64;
    const int f4 = (t & 15) * 4;
    const int i4 = (t >> 4) * 4;

    float c[4][4];
    #pragma unroll
    for (int r = 0; r < 4; ++r) { c[r][0]=0.f; c[r][1]=0.f; c[r][2]=0.f; c[r][3]=0.f; }

    const float4* in4 = reinterpret_cast<const float4*>(input);
    const float4* W4  = reinterpret_cast<const float4*>(W);

    for (int kc = 0; kc < 4; ++kc) {
        __syncthreads();
        #pragma unroll
        for (int r = 0; r < 4; ++r) {
            const int idx = t + r * 256;
            const int row = idx >> 4;
            const int c4  = idx & 15;
            *reinterpret_cast<float4*>(&pool[row * 64 + c4 * 4]) =
                in4[(size_t)(i0 + row) * 64 + kc * 16 + c4];
            *reinterpret_cast<float4*>(&pool[4096 + row * 64 + c4 * 4]) =
                W4[(size_t)(kc * 64 + row) * 16 + c4];
        }
        __syncthreads();
        #pragma unroll 8
        for (int kk = 0; kk < 64; ++kk) {
            const float4 wv = *reinterpret_cast<const float4*>(&pool[4096 + kk * 64 + f4]);
            #pragma unroll
            for (int r = 0; r < 4; ++r) {
                const float iv = pool[(i4 + r) * 64 + kk];
                c[r][0] = fmaf(iv, wv.x, c[r][0]);
                c[r][1] = fmaf(iv, wv.y, c[r][1]);
                c[r][2] = fmaf(iv, wv.z, c[r][2]);
                c[r][3] = fmaf(iv, wv.w, c[r][3]);
            }
        }
    }

    // g_hf32 from registers (tf32-rounded)
    #pragma unroll
    for (int r = 0; r < 4; ++r) {
        float4 v;
        v.x = tf32r(c[r][0]); v.y = tf32r(c[r][1]);
        v.z = tf32r(c[r][2]); v.w = tf32r(c[r][3]);
        *reinterpret_cast<float4*>(g_hf32 + (size_t)(i0 + i4 + r) * FOUT + f4) = v;
    }

    // stage full-precision h into padded smem for exact s1/s2
    __syncthreads();
    #pragma unroll
    for (int r = 0; r < 4; ++r) {
        float* row = &pool[(i4 + r) * 65 + f4];
        row[0] = c[r][0]; row[1] = c[r][1]; row[2] = c[r][2]; row[3] = c[r][3];
    }
    __syncthreads();

    if (t < 64) {
        float s1 = 0.f, s2 = 0.f;
        #pragma unroll 8
        for (int f = 0; f < 64; ++f) {
            const float hv = pool[t * 65 + f];
            s1 = fmaf(hv, __ldg(&a[f]), s1);
            s2 = fmaf(hv, __ldg(&a[64 + f]), s2);
        }
        g_s1[i0 + t] = s1;
        g_s2[i0 + t] = s2;
    }
}

// ============================================================================
// Kernel 2: tf32 HMMA GEMM  part = Wattn @ h  (+ per-row l partials)
// Grid: (64 i-tiles, 4 j-splits), 256 threads = 8 warps, dynamic smem.
// ============================================================================
__global__ __launch_bounds__(256, 2) void k_mma(const int* __restrict__ adj)
{
    extern __shared__ float smem[];
    float* As = smem;                 // [128][68]
    float* Bs = smem + SM_B_OFF;      // [64][68]

    const int t = threadIdx.x;
    const int w = t >> 5;
    const int l = t & 31;
    const int i0 = blockIdx.x * TM;
    const int js = blockIdx.y;
    const int j0 = js * KCHUNK;

    // ---- build mapping: warp covers row pairs p = w + 8k; lane half selects row ----
    const int half = l >> 4;
    const int jq   = (l & 15) * 4;    // j offset within 64-j tile
    int   rowk[8];
    float s1r[8];
    float l_acc[8];
    uint32_t aoff[8];                 // element offset into adj (tile 0)
    int4 pre[8];
    #pragma unroll
    for (int k = 0; k < 8; ++k) {
        rowk[k]  = 2 * (w + 8 * k) + half;
        s1r[k]   = g_s1[i0 + rowk[k]];
        l_acc[k] = 0.f;
        aoff[k]  = (uint32_t)(i0 + rowk[k]) * N_NODES + (uint32_t)(j0 + jq);
        pre[k]   = *reinterpret_cast<const int4*>(adj + aoff[k]);
    }

    // ---- mma mapping ----
    const int gid = l >> 2;
    const int tig = l & 3;
    float c[8][4];
    #pragma unroll
    for (int nt = 0; nt < 8; ++nt) {
        c[nt][0] = 0.f; c[nt][1] = 0.f; c[nt][2] = 0.f; c[nt][3] = 0.f;
    }

    for (int tile = 0; tile < NT; ++tile) {
        const int jt = j0 + tile * TKJ;

        // --- build A (weights, tf32-rounded fp32) ---
        const float4 s2q = *reinterpret_cast<const float4*>(g_s2 + jt + jq);
        #pragma unroll
        for (int k = 0; k < 8; ++k) {
            const int4 av = pre[k];
            if (tile + 1 < NT)
                pre[k] = *reinterpret_cast<const int4*>(
                    adj + aoff[k] + (uint32_t)(tile + 1) * TKJ);

            float x, e, w0, w1, w2, w3;
            x = s1r[k] + s2q.x; e = x > 0.f ? x : GAT_ALPHA * x;
            w0 = tf32r((av.x > 0) ? __expf(e) : EXP_M10);
            x = s1r[k] + s2q.y; e = x > 0.f ? x : GAT_ALPHA * x;
            w1 = tf32r((av.y > 0) ? __expf(e) : EXP_M10);
            x = s1r[k] + s2q.z; e = x > 0.f ? x : GAT_ALPHA * x;
            w2 = tf32r((av.z > 0) ? __expf(e) : EXP_M10);
            x = s1r[k] + s2q.w; e = x > 0.f ? x : GAT_ALPHA * x;
            w3 = tf32r((av.w > 0) ? __expf(e) : EXP_M10);

            l_acc[k] += (w0 + w1) + (w2 + w3);

            float4 v; v.x = w0; v.y = w1; v.z = w2; v.w = w3;
            *reinterpret_cast<float4*>(As + rowk[k] * A_STRIDE + jq) = v;
        }

        // --- stage B tile [64 j][64 f] (already tf32-rounded in g_hf32) ---
        {
            const int br = t >> 2;
            const int q  = t & 3;
            const float* src = g_hf32 + (size_t)(jt + br) * FOUT;
            float* dst = Bs + br * B_STRIDE;
            #pragma unroll
            for (int r2 = 0; r2 < 4; ++r2) {
                const int cq = q * 4 + r2 * 16;
                *reinterpret_cast<float4*>(dst + cq) =
                    *reinterpret_cast<const float4*>(src + cq);
            }
        }

        __syncthreads();

        // --- mma phase: 8 k-steps x 8 n-tiles ---
        #pragma unroll
        for (int ks = 0; ks < 8; ++ks) {
            const int k0 = ks * 8;
            const float* arow = As + (w * 16 + gid) * A_STRIDE + k0 + tig;
            const uint32_t a0 = __float_as_uint(arow[0]);
            const uint32_t a1 = __float_as_uint(arow[8 * A_STRIDE]);
            const uint32_t a2 = __float_as_uint(arow[4]);
            const uint32_t a3 = __float_as_uint(arow[8 * A_STRIDE + 4]);
            const float* brow = Bs + (k0 + tig) * B_STRIDE + gid;
            #pragma unroll
            for (int nt = 0; nt < 8; ++nt) {
                const uint32_t b0 = __float_as_uint(brow[nt * 8]);
                const uint32_t b1 = __float_as_uint(brow[4 * B_STRIDE + nt * 8]);
                mma_tf32(c[nt], a0, a1, a2, a3, b0, b1);
            }
        }

        __syncthreads();
    }

    // --- epilogue: write D partials ---
    #pragma unroll
    for (int nt = 0; nt < 8; ++nt) {
        const int col = nt * 8 + tig * 2;
        float* p0 = &g_part[js][i0 + w * 16 + gid][col];
        float* p1 = &g_part[js][i0 + w * 16 + gid + 8][col];
        *reinterpret_cast<float2*>(p0) = make_float2(c[nt][0], c[nt][1]);
        *reinterpret_cast<float2*>(p1) = make_float2(c[nt][2], c[nt][3]);
    }

    // --- l partials: reduce over the 16 lanes sharing each row ---
    #pragma unroll
    for (int k = 0; k < 8; ++k) {
        float v = l_acc[k];
        v += __shfl_xor_sync(0xffffffffu, v, 1);
        v += __shfl_xor_sync(0xffffffffu, v, 2);
        v += __shfl_xor_sync(0xffffffffu, v, 4);
        v += __shfl_xor_sync(0xffffffffu, v, 8);
        if ((l & 15) == 0) g_lpart[js][i0 + rowk[k]] = v;
    }
}

// ============================================================================
// Kernel 3: reduce 4 partials, normalize, ELU
// ============================================================================
__global__ __launch_bounds__(256) void k_reduce(float* __restrict__ out)
{
    const int idx = blockIdx.x * 256 + threadIdx.x;   // over N*FOUT
    const int i = idx >> 6;
    const int f = idx & 63;

    float s = 0.0f, lsum = 0.0f;
    #pragma unroll
    for (int p = 0; p < JSPLIT; ++p) {
        s    += g_part[p][i][f];
        lsum += g_lpart[p][i];
    }
    const float v = s / lsum;
    out[idx] = (v > 0.0f) ? v : (__expf(v) - 1.0f);
}

// ============================================================================
extern "C" void kernel_launch(void* const* d_in, const int* in_sizes, int n_in,
                              void* d_out, int out_size)
{
    const float* input = (const float*)d_in[0];  // [8192, 256]
    const int*   adj   = (const int*)  d_in[1];  // [8192, 8192]
    const float* W     = (const float*)d_in[2];  // [256, 64]
    const float* a     = (const float*)d_in[3];  // [128, 1]
    float* out = (float*)d_out;                  // [8192, 64]

    cudaFuncSetAttribute(k_mma, cudaFuncAttributeMaxDynamicSharedMemorySize, SMEM_BYTES);

    k_h<<<N_NODES / 64, 256>>>(input, W, a);
    k_mma<<<dim3(N_NODES / TM, JSPLIT), 256, SMEM_BYTES>>>(adj);
    k_reduce<<<(N_NODES * FOUT) / 256, 256>>>(out);
}